// round 1
// baseline (speedup 1.0000x reference)
#include <cuda_runtime.h>
#include <math.h>

#define NB 4
#define LD 4096
#define LE 4096
#define DM 512
#define NH 8
#define DH 64
#define NU 45
#define NTOP 45

// ---------------- scratch (static __device__, no allocation) ----------------
__device__ float g_Q[NB * LD * DM];          // (B, L_DEC, 512)
__device__ float g_K[NB * LE * DM];          // (B, L_ENC, 512)
__device__ float g_V[NB * LE * DM];          // (B, L_ENC, 512)
__device__ float g_M[NB * NH * LD];          // (bh, l)
__device__ int   g_top[NB * NH * NTOP];
__device__ float g_scores[NB * NH * NTOP * LE];
__device__ float g_mx[NB * NH * NTOP];
__device__ float g_se[NB * NH * NTOP];
__device__ float g_upd[NB * NH * NTOP * DH];
__device__ float g_vmean[NB * DM];
__device__ float g_base[NB * DM];

// ---------------- zero scratch that is atomically accumulated ----------------
__global__ void zero_kernel() {
    int i = blockIdx.x * 256 + threadIdx.x;     // grid 360*256 = 92160
    if (i < NB * DM) g_vmean[i] = 0.0f;
    if (i < NB * NH * NTOP * DH) g_upd[i] = 0.0f;
}

// ---------------- fp32 SGEMM: C(M x 512) = A(M x 512) @ W(512 x 512) + b ----
// BM=BN=128, BK=8, 256 threads, 8x8 per-thread tile
__global__ __launch_bounds__(256) void sgemm512(const float* __restrict__ A,
                                                const float* __restrict__ W,
                                                const float* __restrict__ bias,
                                                float* __restrict__ C) {
    __shared__ float As[8][128];
    __shared__ float Bs[8][128];
    const int bm = blockIdx.y * 128;
    const int bn = blockIdx.x * 128;
    const int tid = threadIdx.x;
    const int tx = tid & 15;
    const int ty = tid >> 4;

    float acc[8][8];
#pragma unroll
    for (int i = 0; i < 8; i++)
#pragma unroll
        for (int j = 0; j < 8; j++) acc[i][j] = 0.0f;

    const int arow = tid >> 1;           // 0..127
    const int acol = (tid & 1) * 4;      // 0 or 4
    const int brow = tid >> 5;           // 0..7
    const int bcol = (tid & 31) * 4;     // 0..124

    const float* Ap = A + (size_t)(bm + arow) * DM + acol;
    const float* Bp = W + (size_t)brow * DM + bn + bcol;

    for (int k0 = 0; k0 < DM; k0 += 8) {
        float4 av = *(const float4*)(Ap + k0);
        float4 bv = *(const float4*)(Bp + (size_t)k0 * DM);
        As[acol + 0][arow] = av.x;
        As[acol + 1][arow] = av.y;
        As[acol + 2][arow] = av.z;
        As[acol + 3][arow] = av.w;
        *(float4*)&Bs[brow][bcol] = bv;
        __syncthreads();
#pragma unroll
        for (int k = 0; k < 8; k++) {
            float4 a0 = *(float4*)&As[k][ty * 8];
            float4 a1 = *(float4*)&As[k][ty * 8 + 4];
            float4 b0 = *(float4*)&Bs[k][tx * 8];
            float4 b1 = *(float4*)&Bs[k][tx * 8 + 4];
            float ar[8] = {a0.x, a0.y, a0.z, a0.w, a1.x, a1.y, a1.z, a1.w};
            float br[8] = {b0.x, b0.y, b0.z, b0.w, b1.x, b1.y, b1.z, b1.w};
#pragma unroll
            for (int i = 0; i < 8; i++)
#pragma unroll
                for (int j = 0; j < 8; j++) acc[i][j] += ar[i] * br[j];
        }
        __syncthreads();
    }

    float bj[8];
#pragma unroll
    for (int j = 0; j < 8; j++) bj[j] = bias[bn + tx * 8 + j];
#pragma unroll
    for (int i = 0; i < 8; i++) {
        const int row = bm + ty * 8 + i;
        float4 o0 = make_float4(acc[i][0] + bj[0], acc[i][1] + bj[1],
                                acc[i][2] + bj[2], acc[i][3] + bj[3]);
        float4 o1 = make_float4(acc[i][4] + bj[4], acc[i][5] + bj[5],
                                acc[i][6] + bj[6], acc[i][7] + bj[7]);
        *(float4*)&C[(size_t)row * DM + bn + tx * 8] = o0;
        *(float4*)&C[(size_t)row * DM + bn + tx * 8 + 4] = o1;
    }
}

// ---------------- V column mean --------------------------------------------
__global__ void vmean_kernel() {
    const int b = blockIdx.x >> 5;          // grid NB*32
    const int slab = blockIdx.x & 31;       // 128 rows each
    const int t = threadIdx.x;              // 512
    const float* base = g_V + ((size_t)b * LE + slab * 128) * DM + t;
    float s = 0.0f;
    for (int r = 0; r < 128; r++) s += base[(size_t)r * DM];
    atomicAdd(&g_vmean[b * DM + t], s * (1.0f / (float)LE));
}

// ---------------- ProbSparse sparsity measure M -----------------------------
// one block per (b, l); 128 threads
__global__ void sample_m_kernel(const int* __restrict__ sidx) {
    const int bl = blockIdx.x;
    const int b = bl >> 12;
    const int l = bl & (LD - 1);
    __shared__ float qs[DM];
    __shared__ int idx[NU];
    __shared__ float qk[NH][NU + 3];
    const int t = threadIdx.x;

    ((float4*)qs)[t] = ((const float4*)(g_Q + (size_t)bl * DM))[t];
    if (t < NU) idx[t] = sidx[l * NU + t];
    __syncthreads();

    for (int p = t; p < NU * NH; p += 128) {
        const int u = p >> 3;
        const int h = p & 7;
        const float* kr = g_K + ((size_t)b * LE + idx[u]) * DM + h * DH;
        const float* qr = qs + h * DH;
        float s = 0.0f;
#pragma unroll
        for (int i = 0; i < 16; i++) {
            float4 kv = ((const float4*)kr)[i];
            float4 qv = ((const float4*)qr)[i];
            s += kv.x * qv.x + kv.y * qv.y + kv.z * qv.z + kv.w * qv.w;
        }
        qk[h][u] = s;
    }
    __syncthreads();

    if (t < NH) {
        float mx = -INFINITY, sm = 0.0f;
        for (int u = 0; u < NU; u++) {
            float v = qk[t][u];
            mx = fmaxf(mx, v);
            sm += v;
        }
        g_M[((size_t)(b * NH + t)) * LD + l] = mx - sm * (1.0f / (float)LE);
    }
}

// ---------------- top-k (45 of 4096) per (b,h) ------------------------------
__global__ void topk_kernel() {
    const int bh = blockIdx.x;
    __shared__ float vals[LD];
    __shared__ float rmax[256];
    __shared__ int ridx[256];
    const int t = threadIdx.x;
    for (int i = t; i < LD; i += 256) vals[i] = g_M[(size_t)bh * LD + i];
    __syncthreads();

    for (int it = 0; it < NTOP; it++) {
        float best = -INFINITY;
        int bi = 1 << 30;
        for (int i = t; i < LD; i += 256) {
            float v = vals[i];
            if (v > best || (v == best && i < bi)) { best = v; bi = i; }
        }
        rmax[t] = best;
        ridx[t] = bi;
        __syncthreads();
        for (int s = 128; s > 0; s >>= 1) {
            if (t < s) {
                float v = rmax[t + s];
                int j = ridx[t + s];
                if (v > rmax[t] || (v == rmax[t] && j < ridx[t])) { rmax[t] = v; ridx[t] = j; }
            }
            __syncthreads();
        }
        if (t == 0) {
            g_top[bh * NTOP + it] = ridx[0];
            vals[ridx[0]] = -INFINITY;
        }
        __syncthreads();
    }
}

// ---------------- scores: Q_red(45x64) @ K^T, split over K ------------------
// grid (LE/512, NH, NB), 256 threads; each K row is read exactly once
__global__ void scores_kernel() {
    const int kc = blockIdx.x;
    const int h = blockIdx.y;
    const int b = blockIdx.z;
    const int bh = b * NH + h;
    __shared__ float qs[NU][DH];
    const int t = threadIdx.x;

    for (int p = t; p < NU * 16; p += 256) {
        const int u = p >> 4;
        const int i = p & 15;
        const int l = g_top[bh * NTOP + u];
        ((float4*)qs[u])[i] =
            ((const float4*)(g_Q + ((size_t)b * LD + l) * DM + h * DH))[i];
    }
    __syncthreads();

    for (int kk = kc * 512 + t; kk < kc * 512 + 512; kk += 256) {
        float kr[DH];
        const float4* kp = (const float4*)(g_K + ((size_t)b * LE + kk) * DM + h * DH);
#pragma unroll
        for (int i = 0; i < 16; i++) {
            float4 v = kp[i];
            kr[4 * i + 0] = v.x; kr[4 * i + 1] = v.y;
            kr[4 * i + 2] = v.z; kr[4 * i + 3] = v.w;
        }
        for (int u = 0; u < NU; u++) {
            float s = 0.0f;
#pragma unroll
            for (int d = 0; d < DH; d++) s += kr[d] * qs[u][d];
            g_scores[((size_t)(bh * NTOP + u)) * LE + kk] = s * 0.125f;
        }
    }
}

// ---------------- row max + sum(exp) per (bh,u) -----------------------------
__global__ void stats_kernel() {
    const int row = blockIdx.x;             // 0..1439
    const float* s = g_scores + (size_t)row * LE;
    __shared__ float red[256];
    const int t = threadIdx.x;

    float m = -INFINITY;
    for (int i = t; i < LE; i += 256) m = fmaxf(m, s[i]);
    red[t] = m;
    __syncthreads();
    for (int st = 128; st > 0; st >>= 1) {
        if (t < st) red[t] = fmaxf(red[t], red[t + st]);
        __syncthreads();
    }
    const float mAll = red[0];
    __syncthreads();

    float sum = 0.0f;
    for (int i = t; i < LE; i += 256) sum += expf(s[i] - mAll);
    red[t] = sum;
    __syncthreads();
    for (int st = 128; st > 0; st >>= 1) {
        if (t < st) red[t] += red[t + st];
        __syncthreads();
    }
    if (t == 0) { g_mx[row] = mAll; g_se[row] = red[0]; }
}

// ---------------- upd = softmax(scores) @ V, split over K, atomic merge -----
// grid (LE/512, NH, NB), 256 threads; V read exactly once
__global__ void pv_kernel() {
    const int kc = blockIdx.x;
    const int h = blockIdx.y;
    const int b = blockIdx.z;
    const int bh = b * NH + h;
    const int t = threadIdx.x;

    __shared__ float Vs[64][DH];       // 16 KB
    __shared__ float Ps[NU][64];       // 11.25 KB
    __shared__ float mrow[NU], inv[NU];

    if (t < NU) {
        mrow[t] = g_mx[bh * NTOP + t];
        inv[t] = 1.0f / g_se[bh * NTOP + t];
    }
    __syncthreads();

    float acc[3][4];
#pragma unroll
    for (int it = 0; it < 3; it++)
#pragma unroll
        for (int c = 0; c < 4; c++) acc[it][c] = 0.0f;

    for (int sc = 0; sc < 8; sc++) {
        const int kbase = kc * 512 + sc * 64;
        // load V sub-chunk
        for (int p = t; p < 64 * 16; p += 256) {
            const int kk = p >> 4;
            const int i = p & 15;
            ((float4*)Vs[kk])[i] =
                ((const float4*)(g_V + ((size_t)b * LE + kbase + kk) * DM + h * DH))[i];
        }
        // load + exp P sub-chunk
        for (int p = t; p < NU * 16; p += 256) {
            const int u = p >> 4;
            const int i = p & 15;
            float4 s4 = ((const float4*)(g_scores + ((size_t)(bh * NTOP + u)) * LE + kbase))[i];
            const float m = mrow[u], iv = inv[u];
            float4 pv;
            pv.x = expf(s4.x - m) * iv;
            pv.y = expf(s4.y - m) * iv;
            pv.z = expf(s4.z - m) * iv;
            pv.w = expf(s4.w - m) * iv;
            ((float4*)Ps[u])[i] = pv;
        }
        __syncthreads();
#pragma unroll
        for (int it = 0; it < 3; it++) {
            const int p = t + it * 256;
            if (p < NU * 16) {
                const int u = p >> 4;
                const int d4 = p & 15;
                float a0 = acc[it][0], a1 = acc[it][1], a2 = acc[it][2], a3 = acc[it][3];
                for (int kk = 0; kk < 64; kk++) {
                    const float pw = Ps[u][kk];
                    float4 vv = ((float4*)Vs[kk])[d4];
                    a0 += pw * vv.x; a1 += pw * vv.y;
                    a2 += pw * vv.z; a3 += pw * vv.w;
                }
                acc[it][0] = a0; acc[it][1] = a1; acc[it][2] = a2; acc[it][3] = a3;
            }
        }
        __syncthreads();
    }

#pragma unroll
    for (int it = 0; it < 3; it++) {
        const int p = t + it * 256;
        if (p < NU * 16) {
            const int u = p >> 4;
            const int d4 = p & 15;
            float* dst = g_upd + ((size_t)(bh * NTOP + u)) * DH + d4 * 4;
            atomicAdd(dst + 0, acc[it][0]);
            atomicAdd(dst + 1, acc[it][1]);
            atomicAdd(dst + 2, acc[it][2]);
            atomicAdd(dst + 3, acc[it][3]);
        }
    }
}

// ---------------- base output row per batch: vmean @ Wo + bo ----------------
__global__ void baseout_kernel(const float* __restrict__ Wo, const float* __restrict__ bo) {
    const int b = blockIdx.x;
    const int t = threadIdx.x;   // 512
    float s = bo[t];
    for (int k = 0; k < DM; k++) s += g_vmean[b * DM + k] * Wo[(size_t)k * DM + t];
    g_base[b * DM + t] = s;
}

// ---------------- fill output with base rows --------------------------------
__global__ void fill_kernel(float* __restrict__ out) {
    const size_t bl = blockIdx.x;            // grid NB*LD, 128 threads
    const int b = blockIdx.x >> 12;
    float4 v = ((const float4*)(g_base + b * DM))[threadIdx.x];
    ((float4*)(out + bl * DM))[threadIdx.x] = v;
}

// ---------------- scatter corrections: (upd - vmean_h) @ Wo_h ---------------
// grid (NTOP, NH, NB), 512 threads
__global__ void scatter_kernel(const float* __restrict__ Wo, float* __restrict__ out) {
    const int u = blockIdx.x;
    const int h = blockIdx.y;
    const int b = blockIdx.z;
    const int bh = b * NH + h;
    __shared__ float delta[DH];
    __shared__ int lsh;
    const int t = threadIdx.x;

    if (t == 0) lsh = g_top[bh * NTOP + u];
    if (t < DH)
        delta[t] = g_upd[((size_t)(bh * NTOP + u)) * DH + t] - g_vmean[b * DM + h * DH + t];
    __syncthreads();

    const int l = lsh;
    float s = 0.0f;
#pragma unroll 8
    for (int d = 0; d < DH; d++) s += delta[d] * Wo[(size_t)(h * DH + d) * DM + t];
    atomicAdd(&out[((size_t)b * LD + l) * DM + t], s);
}

// ---------------- launch ----------------------------------------------------
extern "C" void kernel_launch(void* const* d_in, const int* in_sizes, int n_in,
                              void* d_out, int out_size) {
    const float* x       = (const float*)d_in[0];
    const float* context = (const float*)d_in[1];
    const float* Wq      = (const float*)d_in[2];
    const float* bq      = (const float*)d_in[3];
    const float* Wk      = (const float*)d_in[4];
    const float* bk      = (const float*)d_in[5];
    const float* Wv      = (const float*)d_in[6];
    const float* bv      = (const float*)d_in[7];
    const float* Wo      = (const float*)d_in[8];
    const float* bo      = (const float*)d_in[9];
    const int*   sidx    = (const int*)d_in[10];
    float* out = (float*)d_out;

    float *pQ, *pK, *pV;
    cudaGetSymbolAddress((void**)&pQ, g_Q);
    cudaGetSymbolAddress((void**)&pK, g_K);
    cudaGetSymbolAddress((void**)&pV, g_V);

    zero_kernel<<<360, 256>>>();

    dim3 gg(DM / 128, (NB * LD) / 128);
    sgemm512<<<gg, 256>>>(x, Wq, bq, pQ);
    sgemm512<<<gg, 256>>>(context, Wk, bk, pK);
    sgemm512<<<gg, 256>>>(context, Wv, bv, pV);

    vmean_kernel<<<NB * 32, 512>>>();
    sample_m_kernel<<<NB * LD, 128>>>(sidx);
    topk_kernel<<<NB * NH, 256>>>();
    scores_kernel<<<dim3(LE / 512, NH, NB), 256>>>();
    stats_kernel<<<NB * NH * NTOP, 256>>>();
    pv_kernel<<<dim3(LE / 512, NH, NB), 256>>>();
    baseout_kernel<<<NB, 512>>>(Wo, bo);
    fill_kernel<<<NB * LD, 128>>>(out);
    scatter_kernel<<<dim3(NTOP, NH, NB), 512>>>(Wo, out);
}

// round 3
// speedup vs baseline: 1.5460x; 1.5460x over previous
#include <cuda_runtime.h>
#include <stdint.h>
#include <math.h>

#define NB 4
#define LD 4096
#define LE 4096
#define DM 512
#define NH 8
#define DH 64
#define NU 45
#define NTOP 45

// ---------------- scratch (static __device__, no allocation) ----------------
__device__ float g_Q[NB * LD * DM];          // (B, L_DEC, 512)
__device__ float g_K[NB * LE * DM];          // (B, L_ENC, 512)
__device__ float g_V[NB * LE * DM];          // (B, L_ENC, 512)
__device__ float g_M[NB * NH * LD];          // (bh, l)
__device__ int   g_top[NB * NH * NTOP];
__device__ float g_scores[NB * NH * NTOP * LE];
__device__ float g_mx[NB * NH * NTOP];
__device__ float g_se[NB * NH * NTOP];
__device__ float g_upd[NB * NH * NTOP * DH];
__device__ float g_vmean[NB * DM];
__device__ float g_base[NB * DM];

// ---------------- zero scratch that is atomically accumulated ----------------
__global__ void zero_kernel() {
    int i = blockIdx.x * 256 + threadIdx.x;
    if (i < NB * DM) g_vmean[i] = 0.0f;
    if (i < NB * NH * NTOP * DH) g_upd[i] = 0.0f;
}

// ---------------- helpers for tf32 tensor-core GEMM -------------------------
__device__ __forceinline__ uint32_t f2tf32(float v) {
    uint32_t u;
    asm volatile("cvt.rna.tf32.f32 %0, %1;" : "=r"(u) : "f"(v));
    return u;
}

__device__ __forceinline__ void cpasync16(void* smem_dst, const void* gsrc) {
    uint32_t d = (uint32_t)__cvta_generic_to_shared(smem_dst);
    asm volatile("cp.async.cg.shared.global [%0], [%1], 16;" :: "r"(d), "l"(gsrc));
}

#define CP_COMMIT() asm volatile("cp.async.commit_group;")
#define CP_WAIT(N)  asm volatile("cp.async.wait_group %0;" :: "n"(N))

// A smem: [buf][128 rows][36 floats]  (BK=32 + pad 4)
// B smem: [buf][32 rows][136 floats]  (BN=128 + pad 8)
#define AS_STRIDE 36
#define BS_STRIDE 136
#define AS_BUF (128 * AS_STRIDE)
#define BS_BUF (32 * BS_STRIDE)
#define TG_SMEM_BYTES ((2 * AS_BUF + 2 * BS_BUF) * 4)

// ---------------- tf32 tensor-core GEMM: C(Mx512)=A(Mx512)@W(512x512)+b -----
// block 128x128, BK=32, 256 threads = 8 warps (4 x 2), warp tile 32x64
__global__ __launch_bounds__(256) void tgemm512(const float* __restrict__ A,
                                                const float* __restrict__ W,
                                                const float* __restrict__ bias,
                                                float* __restrict__ C) {
    extern __shared__ float sm[];
    float* As = sm;
    float* Bs = sm + 2 * AS_BUF;

    const int bm = blockIdx.y * 128;
    const int bn = blockIdx.x * 128;
    const int tid = threadIdx.x;
    const int lane = tid & 31;
    const int wid = tid >> 5;
    const int wm = (wid & 3) * 32;     // warp row offset in block
    const int wn = (wid >> 2) * 64;    // warp col offset in block
    const int g = lane >> 2;           // 0..7
    const int t4 = lane & 3;           // 0..3

    float acc[2][8][4];
#pragma unroll
    for (int mt = 0; mt < 2; mt++)
#pragma unroll
        for (int nt = 0; nt < 8; nt++)
#pragma unroll
            for (int c = 0; c < 4; c++) acc[mt][nt][c] = 0.0f;

    // ---- tile loaders (cp.async) ----
    const float* Abase = A + (size_t)bm * DM;
    const float* Bbase = W + bn;

#define LOAD_TILE(kt, buf)                                                     \
    do {                                                                       \
        const float* Ag = Abase + (kt) * 32;                                   \
        const float* Bg = Bbase + (size_t)((kt) * 32) * DM;                    \
        _Pragma("unroll")                                                      \
        for (int i = 0; i < 4; i++) {                                          \
            int idx = tid + i * 256;                                           \
            int r = idx >> 3, c = (idx & 7) * 4;                               \
            cpasync16(&As[(buf) * AS_BUF + r * AS_STRIDE + c],                 \
                      Ag + (size_t)r * DM + c);                                \
        }                                                                      \
        _Pragma("unroll")                                                      \
        for (int i = 0; i < 4; i++) {                                          \
            int idx = tid + i * 256;                                           \
            int r = idx >> 5, c = (idx & 31) * 4;                              \
            cpasync16(&Bs[(buf) * BS_BUF + r * BS_STRIDE + c],                 \
                      Bg + (size_t)r * DM + c);                                \
        }                                                                      \
    } while (0)

    LOAD_TILE(0, 0);
    CP_COMMIT();

    for (int kt = 0; kt < 16; kt++) {
        const int buf = kt & 1;
        if (kt < 15) {
            LOAD_TILE(kt + 1, buf ^ 1);
            CP_COMMIT();
            CP_WAIT(1);
        } else {
            CP_WAIT(0);
        }
        __syncthreads();

        const float* Ab = As + buf * AS_BUF;
        const float* Bb = Bs + buf * BS_BUF;
#pragma unroll
        for (int k8 = 0; k8 < 4; k8++) {
            const int kk = k8 * 8;
            uint32_t af[2][4];
#pragma unroll
            for (int mt = 0; mt < 2; mt++) {
                const int rb = wm + mt * 16 + g;
                af[mt][0] = f2tf32(Ab[(rb)*AS_STRIDE + kk + t4]);
                af[mt][1] = f2tf32(Ab[(rb + 8) * AS_STRIDE + kk + t4]);
                af[mt][2] = f2tf32(Ab[(rb)*AS_STRIDE + kk + t4 + 4]);
                af[mt][3] = f2tf32(Ab[(rb + 8) * AS_STRIDE + kk + t4 + 4]);
            }
            uint32_t bf[8][2];
#pragma unroll
            for (int nt = 0; nt < 8; nt++) {
                const int nb = wn + nt * 8 + g;
                bf[nt][0] = f2tf32(Bb[(kk + t4) * BS_STRIDE + nb]);
                bf[nt][1] = f2tf32(Bb[(kk + t4 + 4) * BS_STRIDE + nb]);
            }
#pragma unroll
            for (int mt = 0; mt < 2; mt++)
#pragma unroll
                for (int nt = 0; nt < 8; nt++) {
                    asm volatile(
                        "mma.sync.aligned.m16n8k8.row.col.f32.tf32.tf32.f32 "
                        "{%0,%1,%2,%3}, {%4,%5,%6,%7}, {%8,%9}, {%0,%1,%2,%3};"
                        : "+f"(acc[mt][nt][0]), "+f"(acc[mt][nt][1]),
                          "+f"(acc[mt][nt][2]), "+f"(acc[mt][nt][3])
                        : "r"(af[mt][0]), "r"(af[mt][1]), "r"(af[mt][2]),
                          "r"(af[mt][3]), "r"(bf[nt][0]), "r"(bf[nt][1]));
                }
        }
        __syncthreads();
    }

    // ---- epilogue: bias add + store ----
#pragma unroll
    for (int mt = 0; mt < 2; mt++) {
        const int r0 = bm + wm + mt * 16 + g;
        const int r1 = r0 + 8;
#pragma unroll
        for (int nt = 0; nt < 8; nt++) {
            const int col = bn + wn + nt * 8 + 2 * t4;
            float2 bv = *(const float2*)&bias[col];
            float2 o0 = make_float2(acc[mt][nt][0] + bv.x, acc[mt][nt][1] + bv.y);
            float2 o1 = make_float2(acc[mt][nt][2] + bv.x, acc[mt][nt][3] + bv.y);
            *(float2*)&C[(size_t)r0 * DM + col] = o0;
            *(float2*)&C[(size_t)r1 * DM + col] = o1;
        }
    }
}

// ---------------- V column mean --------------------------------------------
__global__ void vmean_kernel() {
    const int b = blockIdx.x >> 5;
    const int slab = blockIdx.x & 31;
    const int t = threadIdx.x;
    const float* base = g_V + ((size_t)b * LE + slab * 128) * DM + t;
    float s = 0.0f;
    for (int r = 0; r < 128; r++) s += base[(size_t)r * DM];
    atomicAdd(&g_vmean[b * DM + t], s * (1.0f / (float)LE));
}

// ---------------- ProbSparse sparsity measure M -----------------------------
__global__ void sample_m_kernel(const int* __restrict__ sidx) {
    const int bl = blockIdx.x;
    const int b = bl >> 12;
    const int l = bl & (LD - 1);
    __shared__ float qs[DM];
    __shared__ int idx[NU];
    __shared__ float qk[NH][NU + 3];
    const int t = threadIdx.x;

    ((float4*)qs)[t] = ((const float4*)(g_Q + (size_t)bl * DM))[t];
    if (t < NU) idx[t] = sidx[l * NU + t];
    __syncthreads();

    for (int p = t; p < NU * NH; p += 128) {
        const int u = p >> 3;
        const int h = p & 7;
        const float* kr = g_K + ((size_t)b * LE + idx[u]) * DM + h * DH;
        const float* qr = qs + h * DH;
        float s = 0.0f;
#pragma unroll
        for (int i = 0; i < 16; i++) {
            float4 kv = ((const float4*)kr)[i];
            float4 qv = ((const float4*)qr)[i];
            s += kv.x * qv.x + kv.y * qv.y + kv.z * qv.z + kv.w * qv.w;
        }
        qk[h][u] = s;
    }
    __syncthreads();

    if (t < NH) {
        float mx = -INFINITY, sm = 0.0f;
        for (int u = 0; u < NU; u++) {
            float v = qk[t][u];
            mx = fmaxf(mx, v);
            sm += v;
        }
        g_M[((size_t)(b * NH + t)) * LD + l] = mx - sm * (1.0f / (float)LE);
    }
}

// ---------------- top-k (45 of 4096) per (b,h) ------------------------------
__global__ void topk_kernel() {
    const int bh = blockIdx.x;
    __shared__ float vals[LD];
    __shared__ float rmax[256];
    __shared__ int ridx[256];
    const int t = threadIdx.x;
    for (int i = t; i < LD; i += 256) vals[i] = g_M[(size_t)bh * LD + i];
    __syncthreads();

    for (int it = 0; it < NTOP; it++) {
        float best = -INFINITY;
        int bi = 1 << 30;
        for (int i = t; i < LD; i += 256) {
            float v = vals[i];
            if (v > best || (v == best && i < bi)) { best = v; bi = i; }
        }
        rmax[t] = best;
        ridx[t] = bi;
        __syncthreads();
        for (int s = 128; s > 0; s >>= 1) {
            if (t < s) {
                float v = rmax[t + s];
                int j = ridx[t + s];
                if (v > rmax[t] || (v == rmax[t] && j < ridx[t])) { rmax[t] = v; ridx[t] = j; }
            }
            __syncthreads();
        }
        if (t == 0) {
            g_top[bh * NTOP + it] = ridx[0];
            vals[ridx[0]] = -INFINITY;
        }
        __syncthreads();
    }
}

// ---------------- scores: Q_red(45x64) @ K^T, split over K ------------------
__global__ void scores_kernel() {
    const int kc = blockIdx.x;
    const int h = blockIdx.y;
    const int b = blockIdx.z;
    const int bh = b * NH + h;
    __shared__ float qs[NU][DH];
    const int t = threadIdx.x;

    for (int p = t; p < NU * 16; p += 256) {
        const int u = p >> 4;
        const int i = p & 15;
        const int l = g_top[bh * NTOP + u];
        ((float4*)qs[u])[i] =
            ((const float4*)(g_Q + ((size_t)b * LD + l) * DM + h * DH))[i];
    }
    __syncthreads();

    for (int kk = kc * 512 + t; kk < kc * 512 + 512; kk += 256) {
        float kr[DH];
        const float4* kp = (const float4*)(g_K + ((size_t)b * LE + kk) * DM + h * DH);
#pragma unroll
        for (int i = 0; i < 16; i++) {
            float4 v = kp[i];
            kr[4 * i + 0] = v.x; kr[4 * i + 1] = v.y;
            kr[4 * i + 2] = v.z; kr[4 * i + 3] = v.w;
        }
        for (int u = 0; u < NU; u++) {
            float s = 0.0f;
#pragma unroll
            for (int d = 0; d < DH; d++) s += kr[d] * qs[u][d];
            g_scores[((size_t)(bh * NTOP + u)) * LE + kk] = s * 0.125f;
        }
    }
}

// ---------------- row max + sum(exp) per (bh,u) -----------------------------
__global__ void stats_kernel() {
    const int row = blockIdx.x;
    const float* s = g_scores + (size_t)row * LE;
    __shared__ float red[256];
    const int t = threadIdx.x;

    float m = -INFINITY;
    for (int i = t; i < LE; i += 256) m = fmaxf(m, s[i]);
    red[t] = m;
    __syncthreads();
    for (int st = 128; st > 0; st >>= 1) {
        if (t < st) red[t] = fmaxf(red[t], red[t + st]);
        __syncthreads();
    }
    const float mAll = red[0];
    __syncthreads();

    float sum = 0.0f;
    for (int i = t; i < LE; i += 256) sum += expf(s[i] - mAll);
    red[t] = sum;
    __syncthreads();
    for (int st = 128; st > 0; st >>= 1) {
        if (t < st) red[t] += red[t + st];
        __syncthreads();
    }
    if (t == 0) { g_mx[row] = mAll; g_se[row] = red[0]; }
}

// ---------------- upd = softmax(scores) @ V, split over K, atomic merge -----
__global__ void pv_kernel() {
    const int kc = blockIdx.x;
    const int h = blockIdx.y;
    const int b = blockIdx.z;
    const int bh = b * NH + h;
    const int t = threadIdx.x;

    __shared__ float Vs[64][DH];
    __shared__ float Ps[NU][64];
    __shared__ float mrow[NU], inv[NU];

    if (t < NU) {
        mrow[t] = g_mx[bh * NTOP + t];
        inv[t] = 1.0f / g_se[bh * NTOP + t];
    }
    __syncthreads();

    float acc[3][4];
#pragma unroll
    for (int it = 0; it < 3; it++)
#pragma unroll
        for (int c = 0; c < 4; c++) acc[it][c] = 0.0f;

    for (int sc = 0; sc < 8; sc++) {
        const int kbase = kc * 512 + sc * 64;
        for (int p = t; p < 64 * 16; p += 256) {
            const int kk = p >> 4;
            const int i = p & 15;
            ((float4*)Vs[kk])[i] =
                ((const float4*)(g_V + ((size_t)b * LE + kbase + kk) * DM + h * DH))[i];
        }
        for (int p = t; p < NU * 16; p += 256) {
            const int u = p >> 4;
            const int i = p & 15;
            float4 s4 = ((const float4*)(g_scores + ((size_t)(bh * NTOP + u)) * LE + kbase))[i];
            const float m = mrow[u], iv = inv[u];
            float4 pv;
            pv.x = expf(s4.x - m) * iv;
            pv.y = expf(s4.y - m) * iv;
            pv.z = expf(s4.z - m) * iv;
            pv.w = expf(s4.w - m) * iv;
            ((float4*)Ps[u])[i] = pv;
        }
        __syncthreads();
#pragma unroll
        for (int it = 0; it < 3; it++) {
            const int p = t + it * 256;
            if (p < NU * 16) {
                const int u = p >> 4;
                const int d4 = p & 15;
                float a0 = acc[it][0], a1 = acc[it][1], a2 = acc[it][2], a3 = acc[it][3];
                for (int kk = 0; kk < 64; kk++) {
                    const float pw = Ps[u][kk];
                    float4 vv = ((float4*)Vs[kk])[d4];
                    a0 += pw * vv.x; a1 += pw * vv.y;
                    a2 += pw * vv.z; a3 += pw * vv.w;
                }
                acc[it][0] = a0; acc[it][1] = a1; acc[it][2] = a2; acc[it][3] = a3;
            }
        }
        __syncthreads();
    }

#pragma unroll
    for (int it = 0; it < 3; it++) {
        const int p = t + it * 256;
        if (p < NU * 16) {
            const int u = p >> 4;
            const int d4 = p & 15;
            float* dst = g_upd + ((size_t)(bh * NTOP + u)) * DH + d4 * 4;
            atomicAdd(dst + 0, acc[it][0]);
            atomicAdd(dst + 1, acc[it][1]);
            atomicAdd(dst + 2, acc[it][2]);
            atomicAdd(dst + 3, acc[it][3]);
        }
    }
}

// ---------------- base output row per batch: vmean @ Wo + bo ----------------
__global__ void baseout_kernel(const float* __restrict__ Wo, const float* __restrict__ bo) {
    const int b = blockIdx.x;
    const int t = threadIdx.x;
    float s = bo[t];
    for (int k = 0; k < DM; k++) s += g_vmean[b * DM + k] * Wo[(size_t)k * DM + t];
    g_base[b * DM + t] = s;
}

// ---------------- fill output with base rows --------------------------------
__global__ void fill_kernel(float* __restrict__ out) {
    const size_t bl = blockIdx.x;
    const int b = blockIdx.x >> 12;
    float4 v = ((const float4*)(g_base + b * DM))[threadIdx.x];
    ((float4*)(out + bl * DM))[threadIdx.x] = v;
}

// ---------------- scatter corrections: (upd - vmean_h) @ Wo_h ---------------
__global__ void scatter_kernel(const float* __restrict__ Wo, float* __restrict__ out) {
    const int u = blockIdx.x;
    const int h = blockIdx.y;
    const int b = blockIdx.z;
    const int bh = b * NH + h;
    __shared__ float delta[DH];
    __shared__ int lsh;
    const int t = threadIdx.x;

    if (t == 0) lsh = g_top[bh * NTOP + u];
    if (t < DH)
        delta[t] = g_upd[((size_t)(bh * NTOP + u)) * DH + t] - g_vmean[b * DM + h * DH + t];
    __syncthreads();

    const int l = lsh;
    float s = 0.0f;
#pragma unroll 8
    for (int d = 0; d < DH; d++) s += delta[d] * Wo[(size_t)(h * DH + d) * DM + t];
    atomicAdd(&out[((size_t)b * LD + l) * DM + t], s);
}

// ---------------- launch ----------------------------------------------------
extern "C" void kernel_launch(void* const* d_in, const int* in_sizes, int n_in,
                              void* d_out, int out_size) {
    const float* x       = (const float*)d_in[0];
    const float* context = (const float*)d_in[1];
    const float* Wq      = (const float*)d_in[2];
    const float* bq      = (const float*)d_in[3];
    const float* Wk      = (const float*)d_in[4];
    const float* bk      = (const float*)d_in[5];
    const float* Wv      = (const float*)d_in[6];
    const float* bv      = (const float*)d_in[7];
    const float* Wo      = (const float*)d_in[8];
    const float* bo      = (const float*)d_in[9];
    const int*   sidx    = (const int*)d_in[10];
    float* out = (float*)d_out;

    float *pQ, *pK, *pV;
    cudaGetSymbolAddress((void**)&pQ, g_Q);
    cudaGetSymbolAddress((void**)&pK, g_K);
    cudaGetSymbolAddress((void**)&pV, g_V);

    static int smem_set = 0;
    if (!smem_set) {
        cudaFuncSetAttribute(tgemm512, cudaFuncAttributeMaxDynamicSharedMemorySize,
                             TG_SMEM_BYTES);
        smem_set = 1;
    }

    zero_kernel<<<360, 256>>>();

    dim3 gg(DM / 128, (NB * LD) / 128);
    tgemm512<<<gg, 256, TG_SMEM_BYTES>>>(x, Wq, bq, pQ);
    tgemm512<<<gg, 256, TG_SMEM_BYTES>>>(context, Wk, bk, pK);
    tgemm512<<<gg, 256, TG_SMEM_BYTES>>>(context, Wv, bv, pV);

    vmean_kernel<<<NB * 32, 512>>>();
    sample_m_kernel<<<NB * LD, 128>>>(sidx);
    topk_kernel<<<NB * NH, 256>>>();
    scores_kernel<<<dim3(LE / 512, NH, NB), 256>>>();
    stats_kernel<<<NB * NH * NTOP, 256>>>();
    pv_kernel<<<dim3(LE / 512, NH, NB), 256>>>();
    baseout_kernel<<<NB, 512>>>(Wo, bo);
    fill_kernel<<<NB * LD, 128>>>(out);
    scatter_kernel<<<dim3(NTOP, NH, NB), 512>>>(Wo, out);
}

// round 4
// speedup vs baseline: 1.6869x; 1.0911x over previous
#include <cuda_runtime.h>
#include <stdint.h>
#include <math.h>

#define NB 4
#define LD 4096
#define LE 4096
#define DM 512
#define NH 8
#define DH 64
#define NU 45
#define NTOP 45

// ---------------- scratch (static __device__, no allocation) ----------------
__device__ float g_Q[NB * LD * DM];
__device__ float g_K[NB * LE * DM];
__device__ float g_V[NB * LE * DM];
__device__ float g_M[NB * NH * LD];
__device__ int   g_top[NB * NH * NTOP];
__device__ float g_scores[NB * NH * NTOP * LE];   // holds P = exp(s) unnormalized
__device__ float g_se[NB * NH * NTOP];            // row sums of P
__device__ float g_upd[NB * NH * NTOP * DH];      // unnormalized P@V
__device__ float g_vmean[NB * DM];
__device__ float g_base[NB * DM];

// ---------------- zero scratch that is atomically accumulated ----------------
__global__ void zero_kernel() {
    int i = blockIdx.x * 256 + threadIdx.x;
    if (i < NB * DM) g_vmean[i] = 0.0f;
    if (i < NB * NH * NTOP * DH) g_upd[i] = 0.0f;
    if (i < NB * NH * NTOP) g_se[i] = 0.0f;
}

// ---------------- helpers for tf32 tensor-core GEMM -------------------------
__device__ __forceinline__ uint32_t f2tf32(float v) {
    uint32_t u;
    asm volatile("cvt.rna.tf32.f32 %0, %1;" : "=r"(u) : "f"(v));
    return u;
}

__device__ __forceinline__ void cpasync16(void* smem_dst, const void* gsrc) {
    uint32_t d = (uint32_t)__cvta_generic_to_shared(smem_dst);
    asm volatile("cp.async.cg.shared.global [%0], [%1], 16;" :: "r"(d), "l"(gsrc));
}

#define CP_COMMIT() asm volatile("cp.async.commit_group;")
#define CP_WAIT(N)  asm volatile("cp.async.wait_group %0;" :: "n"(N))

#define AS_STRIDE 36
#define BS_STRIDE 136
#define AS_BUF (128 * AS_STRIDE)
#define BS_BUF (32 * BS_STRIDE)
#define TG_SMEM_BYTES ((2 * AS_BUF + 2 * BS_BUF) * 4)

// ---------------- tf32 tensor-core GEMM: C(Mx512)=A(Mx512)@W(512x512)+b -----
__global__ __launch_bounds__(256) void tgemm512(const float* __restrict__ A,
                                                const float* __restrict__ W,
                                                const float* __restrict__ bias,
                                                float* __restrict__ C) {
    extern __shared__ float sm[];
    float* As = sm;
    float* Bs = sm + 2 * AS_BUF;

    const int bm = blockIdx.y * 128;
    const int bn = blockIdx.x * 128;
    const int tid = threadIdx.x;
    const int lane = tid & 31;
    const int wid = tid >> 5;
    const int wm = (wid & 3) * 32;
    const int wn = (wid >> 2) * 64;
    const int g = lane >> 2;
    const int t4 = lane & 3;

    float acc[2][8][4];
#pragma unroll
    for (int mt = 0; mt < 2; mt++)
#pragma unroll
        for (int nt = 0; nt < 8; nt++)
#pragma unroll
            for (int c = 0; c < 4; c++) acc[mt][nt][c] = 0.0f;

    const float* Abase = A + (size_t)bm * DM;
    const float* Bbase = W + bn;

#define LOAD_TILE(kt, buf)                                                     \
    do {                                                                       \
        const float* Ag = Abase + (kt) * 32;                                   \
        const float* Bg = Bbase + (size_t)((kt) * 32) * DM;                    \
        _Pragma("unroll")                                                      \
        for (int i = 0; i < 4; i++) {                                          \
            int idx = tid + i * 256;                                           \
            int r = idx >> 3, c = (idx & 7) * 4;                               \
            cpasync16(&As[(buf) * AS_BUF + r * AS_STRIDE + c],                 \
                      Ag + (size_t)r * DM + c);                                \
        }                                                                      \
        _Pragma("unroll")                                                      \
        for (int i = 0; i < 4; i++) {                                          \
            int idx = tid + i * 256;                                           \
            int r = idx >> 5, c = (idx & 31) * 4;                              \
            cpasync16(&Bs[(buf) * BS_BUF + r * BS_STRIDE + c],                 \
                      Bg + (size_t)r * DM + c);                                \
        }                                                                      \
    } while (0)

    LOAD_TILE(0, 0);
    CP_COMMIT();

    for (int kt = 0; kt < 16; kt++) {
        const int buf = kt & 1;
        if (kt < 15) {
            LOAD_TILE(kt + 1, buf ^ 1);
            CP_COMMIT();
            CP_WAIT(1);
        } else {
            CP_WAIT(0);
        }
        __syncthreads();

        const float* Ab = As + buf * AS_BUF;
        const float* Bb = Bs + buf * BS_BUF;
#pragma unroll
        for (int k8 = 0; k8 < 4; k8++) {
            const int kk = k8 * 8;
            uint32_t af[2][4];
#pragma unroll
            for (int mt = 0; mt < 2; mt++) {
                const int rb = wm + mt * 16 + g;
                af[mt][0] = f2tf32(Ab[(rb)*AS_STRIDE + kk + t4]);
                af[mt][1] = f2tf32(Ab[(rb + 8) * AS_STRIDE + kk + t4]);
                af[mt][2] = f2tf32(Ab[(rb)*AS_STRIDE + kk + t4 + 4]);
                af[mt][3] = f2tf32(Ab[(rb + 8) * AS_STRIDE + kk + t4 + 4]);
            }
            uint32_t bf[8][2];
#pragma unroll
            for (int nt = 0; nt < 8; nt++) {
                const int nb = wn + nt * 8 + g;
                bf[nt][0] = f2tf32(Bb[(kk + t4) * BS_STRIDE + nb]);
                bf[nt][1] = f2tf32(Bb[(kk + t4 + 4) * BS_STRIDE + nb]);
            }
#pragma unroll
            for (int mt = 0; mt < 2; mt++)
#pragma unroll
                for (int nt = 0; nt < 8; nt++) {
                    asm volatile(
                        "mma.sync.aligned.m16n8k8.row.col.f32.tf32.tf32.f32 "
                        "{%0,%1,%2,%3}, {%4,%5,%6,%7}, {%8,%9}, {%0,%1,%2,%3};"
                        : "+f"(acc[mt][nt][0]), "+f"(acc[mt][nt][1]),
                          "+f"(acc[mt][nt][2]), "+f"(acc[mt][nt][3])
                        : "r"(af[mt][0]), "r"(af[mt][1]), "r"(af[mt][2]),
                          "r"(af[mt][3]), "r"(bf[nt][0]), "r"(bf[nt][1]));
                }
        }
        __syncthreads();
    }

#pragma unroll
    for (int mt = 0; mt < 2; mt++) {
        const int r0 = bm + wm + mt * 16 + g;
        const int r1 = r0 + 8;
#pragma unroll
        for (int nt = 0; nt < 8; nt++) {
            const int col = bn + wn + nt * 8 + 2 * t4;
            float2 bv = *(const float2*)&bias[col];
            float2 o0 = make_float2(acc[mt][nt][0] + bv.x, acc[mt][nt][1] + bv.y);
            float2 o1 = make_float2(acc[mt][nt][2] + bv.x, acc[mt][nt][3] + bv.y);
            *(float2*)&C[(size_t)r0 * DM + col] = o0;
            *(float2*)&C[(size_t)r1 * DM + col] = o1;
        }
    }
}

// ---------------- V column mean --------------------------------------------
__global__ void vmean_kernel() {
    const int b = blockIdx.x >> 5;
    const int slab = blockIdx.x & 31;
    const int t = threadIdx.x;
    const float* base = g_V + ((size_t)b * LE + slab * 128) * DM + t;
    float s = 0.0f;
    for (int r = 0; r < 128; r++) s += base[(size_t)r * DM];
    atomicAdd(&g_vmean[b * DM + t], s * (1.0f / (float)LE));
}

// ---------------- ProbSparse sparsity measure M -----------------------------
__global__ void sample_m_kernel(const int* __restrict__ sidx) {
    const int bl = blockIdx.x;
    const int b = bl >> 12;
    const int l = bl & (LD - 1);
    __shared__ float qs[DM];
    __shared__ int idx[NU];
    __shared__ float qk[NH][NU + 3];
    const int t = threadIdx.x;

    ((float4*)qs)[t] = ((const float4*)(g_Q + (size_t)bl * DM))[t];
    if (t < NU) idx[t] = sidx[l * NU + t];
    __syncthreads();

    for (int p = t; p < NU * NH; p += 128) {
        const int u = p >> 3;
        const int h = p & 7;
        const float* kr = g_K + ((size_t)b * LE + idx[u]) * DM + h * DH;
        const float* qr = qs + h * DH;
        float s = 0.0f;
#pragma unroll
        for (int i = 0; i < 16; i++) {
            float4 kv = ((const float4*)kr)[i];
            float4 qv = ((const float4*)qr)[i];
            s += kv.x * qv.x + kv.y * qv.y + kv.z * qv.z + kv.w * qv.w;
        }
        qk[h][u] = s;
    }
    __syncthreads();

    if (t < NH) {
        float mx = -INFINITY, sm = 0.0f;
        for (int u = 0; u < NU; u++) {
            float v = qk[t][u];
            mx = fmaxf(mx, v);
            sm += v;
        }
        g_M[((size_t)(b * NH + t)) * LD + l] = mx - sm * (1.0f / (float)LE);
    }
}

// ---------------- top-k (45 of 4096) per (b,h) ------------------------------
__global__ void topk_kernel() {
    const int bh = blockIdx.x;
    __shared__ float vals[LD];
    __shared__ float rmax[256];
    __shared__ int ridx[256];
    const int t = threadIdx.x;
    for (int i = t; i < LD; i += 256) vals[i] = g_M[(size_t)bh * LD + i];
    __syncthreads();

    for (int it = 0; it < NTOP; it++) {
        float best = -INFINITY;
        int bi = 1 << 30;
        for (int i = t; i < LD; i += 256) {
            float v = vals[i];
            if (v > best || (v == best && i < bi)) { best = v; bi = i; }
        }
        rmax[t] = best;
        ridx[t] = bi;
        __syncthreads();
        for (int s = 128; s > 0; s >>= 1) {
            if (t < s) {
                float v = rmax[t + s];
                int j = ridx[t + s];
                if (v > rmax[t] || (v == rmax[t] && j < ridx[t])) { rmax[t] = v; ridx[t] = j; }
            }
            __syncthreads();
        }
        if (t == 0) {
            g_top[bh * NTOP + it] = ridx[0];
            vals[ridx[0]] = -INFINITY;
        }
        __syncthreads();
    }
}

// ---------------- P = exp(Q_red @ K^T / 8), split over K --------------------
// no max subtraction needed: |s| <= 8 by Cauchy-Schwarz, exp cannot overflow
__global__ void scores_exp_kernel() {
    const int kc = blockIdx.x;
    const int h = blockIdx.y;
    const int b = blockIdx.z;
    const int bh = b * NH + h;
    __shared__ float qs[NU][DH];
    const int t = threadIdx.x;

    for (int p = t; p < NU * 16; p += 256) {
        const int u = p >> 4;
        const int i = p & 15;
        const int l = g_top[bh * NTOP + u];
        ((float4*)qs[u])[i] =
            ((const float4*)(g_Q + ((size_t)b * LD + l) * DM + h * DH))[i];
    }
    __syncthreads();

    for (int kk = kc * 512 + t; kk < kc * 512 + 512; kk += 256) {
        float kr[DH];
        const float4* kp = (const float4*)(g_K + ((size_t)b * LE + kk) * DM + h * DH);
#pragma unroll
        for (int i = 0; i < 16; i++) {
            float4 v = kp[i];
            kr[4 * i + 0] = v.x; kr[4 * i + 1] = v.y;
            kr[4 * i + 2] = v.z; kr[4 * i + 3] = v.w;
        }
        for (int u = 0; u < NU; u++) {
            float s = 0.0f;
#pragma unroll
            for (int d = 0; d < DH; d++) s += kr[d] * qs[u][d];
            g_scores[((size_t)(bh * NTOP + u)) * LE + kk] = __expf(s * 0.125f);
        }
    }
}

// ---------------- row sums of P per (bh,u) ----------------------------------
__global__ void sum_kernel() {
    const int row = blockIdx.x;             // 0..1439
    const float* s = g_scores + (size_t)row * LE;
    __shared__ float red[256];
    const int t = threadIdx.x;

    float sum = 0.0f;
    for (int i = t * 4; i < LE; i += 1024) {
        float4 v = *(const float4*)(s + i);
        sum += v.x + v.y + v.z + v.w;
    }
    red[t] = sum;
    __syncthreads();
    for (int st = 128; st > 0; st >>= 1) {
        if (t < st) red[t] += red[t + st];
        __syncthreads();
    }
    if (t == 0) g_se[row] = red[0];
}

// ---------------- upd_raw = P @ V (unnormalized), split over K --------------
__global__ void pv_kernel() {
    const int kc = blockIdx.x;
    const int h = blockIdx.y;
    const int b = blockIdx.z;
    const int bh = b * NH + h;
    const int t = threadIdx.x;

    __shared__ float Vs[64][DH];
    __shared__ float Ps[NU][64];

    float acc[3][4];
#pragma unroll
    for (int it = 0; it < 3; it++)
#pragma unroll
        for (int c = 0; c < 4; c++) acc[it][c] = 0.0f;

    for (int sc = 0; sc < 8; sc++) {
        const int kbase = kc * 512 + sc * 64;
        for (int p = t; p < 64 * 16; p += 256) {
            const int kk = p >> 4;
            const int i = p & 15;
            ((float4*)Vs[kk])[i] =
                ((const float4*)(g_V + ((size_t)b * LE + kbase + kk) * DM + h * DH))[i];
        }
        for (int p = t; p < NU * 16; p += 256) {
            const int u = p >> 4;
            const int i = p & 15;
            ((float4*)Ps[u])[i] =
                ((const float4*)(g_scores + ((size_t)(bh * NTOP + u)) * LE + kbase))[i];
        }
        __syncthreads();
#pragma unroll
        for (int it = 0; it < 3; it++) {
            const int p = t + it * 256;
            if (p < NU * 16) {
                const int u = p >> 4;
                const int d4 = p & 15;
                float a0 = acc[it][0], a1 = acc[it][1], a2 = acc[it][2], a3 = acc[it][3];
                for (int kk = 0; kk < 64; kk++) {
                    const float pw = Ps[u][kk];
                    float4 vv = ((float4*)Vs[kk])[d4];
                    a0 += pw * vv.x; a1 += pw * vv.y;
                    a2 += pw * vv.z; a3 += pw * vv.w;
                }
                acc[it][0] = a0; acc[it][1] = a1; acc[it][2] = a2; acc[it][3] = a3;
            }
        }
        __syncthreads();
    }

#pragma unroll
    for (int it = 0; it < 3; it++) {
        const int p = t + it * 256;
        if (p < NU * 16) {
            const int u = p >> 4;
            const int d4 = p & 15;
            float* dst = g_upd + ((size_t)(bh * NTOP + u)) * DH + d4 * 4;
            atomicAdd(dst + 0, acc[it][0]);
            atomicAdd(dst + 1, acc[it][1]);
            atomicAdd(dst + 2, acc[it][2]);
            atomicAdd(dst + 3, acc[it][3]);
        }
    }
}

// ---------------- base output row per batch: vmean @ Wo + bo ----------------
__global__ void baseout_kernel(const float* __restrict__ Wo, const float* __restrict__ bo) {
    const int b = blockIdx.x;
    const int t = threadIdx.x;
    float s = bo[t];
    for (int k = 0; k < DM; k++) s += g_vmean[b * DM + k] * Wo[(size_t)k * DM + t];
    g_base[b * DM + t] = s;
}

// ---------------- fill output with base rows --------------------------------
__global__ void fill_kernel(float* __restrict__ out) {
    const size_t bl = blockIdx.x;
    const int b = blockIdx.x >> 12;
    float4 v = ((const float4*)(g_base + b * DM))[threadIdx.x];
    ((float4*)(out + bl * DM))[threadIdx.x] = v;
}

// ---------------- scatter corrections: (upd/se - vmean_h) @ Wo_h ------------
__global__ void scatter_kernel(const float* __restrict__ Wo, float* __restrict__ out) {
    const int u = blockIdx.x;
    const int h = blockIdx.y;
    const int b = blockIdx.z;
    const int bh = b * NH + h;
    __shared__ float delta[DH];
    __shared__ int lsh;
    __shared__ float inv_sh;
    const int t = threadIdx.x;

    if (t == 0) {
        lsh = g_top[bh * NTOP + u];
        inv_sh = 1.0f / g_se[bh * NTOP + u];
    }
    __syncthreads();
    if (t < DH)
        delta[t] = g_upd[((size_t)(bh * NTOP + u)) * DH + t] * inv_sh
                 - g_vmean[b * DM + h * DH + t];
    __syncthreads();

    const int l = lsh;
    float s = 0.0f;
#pragma unroll 8
    for (int d = 0; d < DH; d++) s += delta[d] * Wo[(size_t)(h * DH + d) * DM + t];
    atomicAdd(&out[((size_t)b * LD + l) * DM + t], s);
}

// ---------------- launch ----------------------------------------------------
extern "C" void kernel_launch(void* const* d_in, const int* in_sizes, int n_in,
                              void* d_out, int out_size) {
    const float* x       = (const float*)d_in[0];
    const float* context = (const float*)d_in[1];
    const float* Wq      = (const float*)d_in[2];
    const float* bq      = (const float*)d_in[3];
    const float* Wk      = (const float*)d_in[4];
    const float* bk      = (const float*)d_in[5];
    const float* Wv      = (const float*)d_in[6];
    const float* bv      = (const float*)d_in[7];
    const float* Wo      = (const float*)d_in[8];
    const float* bo      = (const float*)d_in[9];
    const int*   sidx    = (const int*)d_in[10];
    float* out = (float*)d_out;

    float *pQ, *pK, *pV;
    cudaGetSymbolAddress((void**)&pQ, g_Q);
    cudaGetSymbolAddress((void**)&pK, g_K);
    cudaGetSymbolAddress((void**)&pV, g_V);

    static int inited = 0;
    static cudaStream_t s1;
    static cudaEvent_t ev0, evV, evFill;
    if (!inited) {
        cudaFuncSetAttribute(tgemm512, cudaFuncAttributeMaxDynamicSharedMemorySize,
                             TG_SMEM_BYTES);
        cudaStreamCreateWithFlags(&s1, cudaStreamNonBlocking);
        cudaEventCreateWithFlags(&ev0, cudaEventDisableTiming);
        cudaEventCreateWithFlags(&evV, cudaEventDisableTiming);
        cudaEventCreateWithFlags(&evFill, cudaEventDisableTiming);
        inited = 1;
    }

    // ---- main stream (0): zero, Q/K GEMMs, sampling path ----
    zero_kernel<<<360, 256>>>();
    cudaEventRecord(ev0, 0);

    // ---- side stream: V-GEMM -> vmean -> baseout -> fill (off critical path)
    cudaStreamWaitEvent(s1, ev0, 0);
    tgemm512<<<dim3(DM / 128, (NB * LE) / 128), 256, TG_SMEM_BYTES, s1>>>(context, Wv, bv, pV);
    cudaEventRecord(evV, s1);
    vmean_kernel<<<NB * 32, 512, 0, s1>>>();
    baseout_kernel<<<NB, 512, 0, s1>>>(Wo, bo);
    fill_kernel<<<NB * LD, 128, 0, s1>>>(out);
    cudaEventRecord(evFill, s1);

    // ---- main stream: critical path ----
    dim3 gg(DM / 128, (NB * LD) / 128);
    tgemm512<<<gg, 256, TG_SMEM_BYTES>>>(x, Wq, bq, pQ);
    tgemm512<<<gg, 256, TG_SMEM_BYTES>>>(context, Wk, bk, pK);

    sample_m_kernel<<<NB * LD, 128>>>(sidx);
    topk_kernel<<<NB * NH, 256>>>();
    scores_exp_kernel<<<dim3(LE / 512, NH, NB), 256>>>();
    sum_kernel<<<NB * NH * NTOP, 256>>>();

    cudaStreamWaitEvent(0, evV, 0);       // pv needs V
    pv_kernel<<<dim3(LE / 512, NH, NB), 256>>>();

    cudaStreamWaitEvent(0, evFill, 0);    // scatter writes over filled output
    scatter_kernel<<<dim3(NTOP, NH, NB), 512>>>(Wo, out);
}